// round 15
// baseline (speedup 1.0000x reference)
#include <cuda_runtime.h>
#include <cuda_bf16.h>
#include <cuda_fp16.h>
#include <math.h>
#include <stdint.h>

// ---------------------------------------------------------------------------
// Problem constants
// ---------------------------------------------------------------------------
#define BATCH   32
#define CDIM    1024
#define HDIM    8
#define INF     8192
#define OUTF    8192
#define NTOT    (3 * OUTF)      // 24576 (q | k | v columns)
#define DK      8

// HMMA GEMM tiling (R11 config)
#define BN      128
#define KSPLIT  8
#define KCHUNK  (INF / KSPLIT)  // 1024
#define KBLK    32
#define NSTAGES (KCHUNK / KBLK) // 32
#define PIPEW   3
#define GEMM_THREADS 256
#define WSTR    40
#define STAGEF  (16 * WSTR)
#define SMEM_BYTES (8 * PIPEW * STAGEF * 4)   // 61440

// Attention
#define ECHUNKS 8
#define EROWS   (CDIM / ECHUNKS)  // 128
#define ATT_THREADS 256

// ---------------------------------------------------------------------------
// Device scratch
// ---------------------------------------------------------------------------
__device__ float g_part[KSPLIT * BATCH * NTOT];          // 25 MB gemm partials
__device__ float g_qkv[BATCH * NTOT];                    // 3 MB
__device__ float g_opart[BATCH * ECHUNKS * CDIM * HDIM]; // 8.4 MB
// x packed in mma-B-fragment order, hi/lo interleaved per fragment
__device__ uint4 g_xpk[512 * 4 * 32];                    // 1 MB
// K packed in mma-A-fragment order (fp16 hi/lo, scale 1/sqrt(8) folded)
__device__ uint4 g_kpk[BATCH * 64 * 32];                 // 1 MB

// ---------------------------------------------------------------------------
// Helpers
// ---------------------------------------------------------------------------
__device__ __forceinline__ void mma_bf16(float* c,
                                         uint32_t a0, uint32_t a1, uint32_t a2, uint32_t a3,
                                         uint32_t b0, uint32_t b1) {
    asm volatile(
        "mma.sync.aligned.m16n8k16.row.col.f32.bf16.bf16.f32 "
        "{%0,%1,%2,%3}, {%4,%5,%6,%7}, {%8,%9}, {%0,%1,%2,%3};"
        : "+f"(c[0]), "+f"(c[1]), "+f"(c[2]), "+f"(c[3])
        : "r"(a0), "r"(a1), "r"(a2), "r"(a3), "r"(b0), "r"(b1));
}

// m16n8k8 fp16 mma, fp32 accumulate
__device__ __forceinline__ void mma8(float* c, uint32_t a0, uint32_t a1, uint32_t b0) {
    asm volatile(
        "mma.sync.aligned.m16n8k8.row.col.f32.f16.f16.f32 "
        "{%0,%1,%2,%3}, {%4,%5}, {%6}, {%0,%1,%2,%3};"
        : "+f"(c[0]), "+f"(c[1]), "+f"(c[2]), "+f"(c[3])
        : "r"(a0), "r"(a1), "r"(b0));
}

// split fp32 pair -> (hi bf16x2 via truncation, lo bf16x2 rn)   [GEMM path]
__device__ __forceinline__ void split2(float2 v, uint32_t& hi, uint32_t& lo) {
    uint32_t u0 = __float_as_uint(v.x);
    uint32_t u1 = __float_as_uint(v.y);
    hi = __byte_perm(u0, u1, 0x7632);
    float h0 = __uint_as_float(u0 & 0xFFFF0000u);
    float h1 = __uint_as_float(u1 & 0xFFFF0000u);
    float l0 = v.x - h0;
    float l1 = v.y - h1;
    asm("cvt.rn.bf16x2.f32 %0, %1, %2;" : "=r"(lo) : "f"(l1), "f"(l0));
}

__device__ __forceinline__ uint32_t h2u(__half2 h) {
    return *reinterpret_cast<uint32_t*>(&h);
}

// split fp32 pair -> fp16x2 hi (rn) + fp16x2 lo (rn of residual)
__device__ __forceinline__ void split2h(float a, float b, uint32_t& hi, uint32_t& lo) {
    __half2 h = __floats2half2_rn(a, b);
    float2 f = __half22float2(h);
    __half2 l = __floats2half2_rn(a - f.x, b - f.y);
    hi = h2u(h); lo = h2u(l);
}

__device__ __forceinline__ uint32_t smem_u32(const void* p) {
    uint32_t a;
    asm("{ .reg .u64 t; cvta.to.shared.u64 t, %1; cvt.u32.u64 %0, t; }"
        : "=r"(a) : "l"(p));
    return a;
}

__device__ __forceinline__ void cp16(uint32_t daddr, const void* src) {
    asm volatile("cp.async.cg.shared.global [%0], [%1], 16;"
                 :: "r"(daddr), "l"(src) : "memory");
}

// ---------------------------------------------------------------------------
// Kernel 0: pack x fp32 -> bf16 hi/lo B-fragments, hi/lo interleaved
// ---------------------------------------------------------------------------
__global__ void pack_x_kernel(const float* __restrict__ x)
{
    int t    = blockIdx.x * blockDim.x + threadIdx.x;
    int lane = t & 31;
    int nb   = (t >> 5) & 3;
    int kb   = t >> 7;

    int n    = nb * 8 + (lane >> 2);
    int kcol = kb * 16 + 2 * (lane & 3);

    const float* xr = x + (size_t)n * INF + kcol;
    float2 v0 = *(const float2*)xr;
    float2 v1 = *(const float2*)(xr + 8);

    uint32_t h0, l0, h1, l1;
    split2(v0, h0, l0);
    split2(v1, h1, l1);

    g_xpk[(size_t)(kb * 4 + nb) * 32 + lane] = make_uint4(h0, h1, l0, l1);
}

// ---------------------------------------------------------------------------
// Kernel 1: QKV GEMM (per-warp cp.async depth-3, occ 3; x-frags via LDG.128)
// ---------------------------------------------------------------------------
__global__ void __launch_bounds__(GEMM_THREADS, 3)
qkv_hmma_kernel(const float* __restrict__ Wq,
                const float* __restrict__ Wk,
                const float* __restrict__ Wv)
{
    extern __shared__ __align__(16) float sW[];

    const int tid  = threadIdx.x;
    const int wid  = tid >> 5;
    const int lane = tid & 31;
    const int g    = lane >> 2;
    const int q    = lane & 3;

    const int nt = blockIdx.x;
    const int kc = blockIdx.y;
    const int wsel = nt >> 6;
    const float* __restrict__ W = (wsel == 0) ? Wq : ((wsel == 1) ? Wk : Wv);
    const int n0     = (nt & 63) * BN;
    const int nglob0 = nt * BN;
    const int kbase  = kc * KCHUNK;
    const int kb0    = kc * (KCHUNK / 16);

    float* wtile = sW + wid * (PIPEW * STAGEF);

    const int lr = lane >> 1;
    const int lh = (lane & 1) * 16;
    const float* wsrc = W + (size_t)(n0 + wid * 16 + lr) * INF + kbase + lh;
    const uint32_t swb = smem_u32(wtile) + (uint32_t)(lr * WSTR + lh) * 4;

    const uint4* __restrict__ xpk = g_xpk;

    float c[4][4];
#pragma unroll
    for (int i = 0; i < 4; i++)
#pragma unroll
        for (int j = 0; j < 4; j++) c[i][j] = 0.0f;

#define ISSUE(T)                                                              \
    do {                                                                      \
        int _t = (T);                                                         \
        if (_t < NSTAGES) {                                                   \
            uint32_t _d = swb + (_t % PIPEW) * (STAGEF * 4);                  \
            const float* _s = wsrc + _t * KBLK;                               \
            cp16(_d,      _s);                                                \
            cp16(_d + 16, _s + 4);                                            \
            cp16(_d + 32, _s + 8);                                            \
            cp16(_d + 48, _s + 12);                                           \
        }                                                                     \
        asm volatile("cp.async.commit_group;" ::: "memory");                  \
    } while (0)

    ISSUE(0);
    ISSUE(1);

#pragma unroll 1
    for (int t = 0; t < NSTAGES; t++) {
        asm volatile("cp.async.wait_group 1;" ::: "memory");
        __syncwarp();

        ISSUE(t + 2);

        const float* Ws = wtile + (t % PIPEW) * STAGEF;

#pragma unroll
        for (int ks = 0; ks < 2; ks++) {
            const int kb = kb0 + t * 2 + ks;
            const int fA = g * WSTR + ks * 16 + 2 * q;
            float2 p0 = *(const float2*)(Ws + fA);
            float2 p1 = *(const float2*)(Ws + fA + 8 * WSTR);
            float2 p2 = *(const float2*)(Ws + fA + 8);
            float2 p3 = *(const float2*)(Ws + fA + 8 * WSTR + 8);
            uint32_t ah0, al0, ah1, al1, ah2, al2, ah3, al3;
            split2(p0, ah0, al0);
            split2(p1, ah1, al1);
            split2(p2, ah2, al2);
            split2(p3, ah3, al3);
#pragma unroll
            for (int n2 = 0; n2 < 4; n2++) {
                uint4 bx = xpk[(size_t)(kb * 4 + n2) * 32 + lane];
                mma_bf16(c[n2], ah0, ah1, ah2, ah3, bx.x, bx.y);
                mma_bf16(c[n2], ah0, ah1, ah2, ah3, bx.z, bx.w);
                mma_bf16(c[n2], al0, al1, al2, al3, bx.x, bx.y);
            }
        }
    }
#undef ISSUE

    float* P = g_part + (size_t)kc * (BATCH * NTOT);
    const int n_lo = nglob0 + wid * 16 + g;
    const int n_hi = n_lo + 8;
#pragma unroll
    for (int n2 = 0; n2 < 4; n2++) {
        const int b0 = n2 * 8 + 2 * q;
        P[(size_t)b0 * NTOT + n_lo]       = c[n2][0];
        P[(size_t)(b0 + 1) * NTOT + n_lo] = c[n2][1];
        P[(size_t)b0 * NTOT + n_hi]       = c[n2][2];
        P[(size_t)(b0 + 1) * NTOT + n_hi] = c[n2][3];
    }
}

// ---------------------------------------------------------------------------
// Kernel 2: reduce K-chunk partials + bias -> g_qkv, AND scatter packed
//   fp16 hi/lo K-fragments into g_kpk. 1 float4/thread, grid 768 (max TLP).
// ---------------------------------------------------------------------------
__global__ void reduce_bias_kernel(const float* __restrict__ bq,
                                   const float* __restrict__ bk,
                                   const float* __restrict__ bv)
{
    const int idx4 = blockIdx.x * blockDim.x + threadIdx.x;  // 0..196607
    const int flat = idx4 * 4;
    const int bb   = flat / NTOT;
    const int n    = flat % NTOT;

    uint32_t* kpk32 = (uint32_t*)g_kpk;
    const float4* P = (const float4*)g_part;

    float4 s = P[idx4];
#pragma unroll
    for (int kc = 1; kc < KSPLIT; kc++) {
        float4 v = P[idx4 + (size_t)kc * (BATCH * NTOT / 4)];
        s.x += v.x; s.y += v.y; s.z += v.z; s.w += v.w;
    }

    const int wsel = n / OUTF;
    const int nr   = n % OUTF;
    const float* bias = (wsel == 0) ? bq : ((wsel == 1) ? bk : bv);
    float4 bbv = *(const float4*)&bias[nr];
    s.x += bbv.x; s.y += bbv.y; s.z += bbv.z; s.w += bbv.w;

    ((float4*)g_qkv)[idx4] = s;

    if (wsel == 1) {
        const int r  = nr >> 3;
        const int j  = (nr & 7) >> 2;
        const int tile = r >> 4;
        const int rr   = r & 15;
        const int comp = rr >> 3;
        const int g    = rr & 7;
        const float sc = 0.35355339059327373f;   // 1/sqrt(8)

        uint32_t h0, l0, h1, l1;
        split2h(s.x * sc, s.y * sc, h0, l0);
        split2h(s.z * sc, s.w * sc, h1, l1);
        const int t0 = 2 * j;
        uint32_t base0 = (((uint32_t)(bb * 64 + tile) * 32) + (g * 4 + t0)) * 4;
        uint32_t base1 = base0 + 4;
        kpk32[base0 + comp]     = h0;
        kpk32[base0 + 2 + comp] = l0;
        kpk32[base1 + comp]     = h1;
        kpk32[base1 + 2 + comp] = l1;
    }
}

// ---------------------------------------------------------------------------
// Kernel 3: HMMA attention, double-pass (16 e's per round), parity-buffered
//   reduce. Score MMAs split into 2 independent chains per group to cut the
//   RAW critical path (3x HMMA lat -> 2x HMMA lat + FADD).
// ---------------------------------------------------------------------------
__global__ void __launch_bounds__(ATT_THREADS, 2)
attention_kernel()
{
    __shared__ float red[2][128];   // [parity][warp*16 + idx]

    const int tid  = threadIdx.x;
    const int w    = tid >> 5;
    const int lane = tid & 31;
    const int g    = lane >> 2;
    const int t    = lane & 3;
    const int b    = blockIdx.x;
    const int ec   = blockIdx.y;

    const float* __restrict__ qb = g_qkv + (size_t)b * NTOT;
    const float* __restrict__ vb = qb + 2 * OUTF;
    const uint4* __restrict__ kpkb = g_kpk + (size_t)b * 2048;

    float out[8][4];
#pragma unroll
    for (int j = 0; j < 8; j++)
#pragma unroll
        for (int i = 0; i < 4; i++) out[j][i] = 0.0f;

#pragma unroll 1
    for (int p = 0; p < EROWS / 16; p++) {     // 8 rounds of 16 e's
        const int eA = ec * EROWS + p * 16;
        const int eB = eA + 8;
        float* rp = red[p & 1];

        float2 qvA = *(const float2*)(qb + (size_t)(eA + g) * HDIM + 2 * t);
        float2 qvB = *(const float2*)(qb + (size_t)(eB + g) * HDIM + 2 * t);
        uint32_t qAh, qAl, qBh, qBl;
        split2h(qvA.x, qvA.y, qAh, qAl);
        split2h(qvB.x, qvB.y, qBh, qBl);

        uint32_t paA0[8], paA1[8], paB0[8], paB1[8];
        float d0A = 0.f, d1A = 0.f, d0B = 0.f, d1B = 0.f;

#pragma unroll
        for (int j = 0; j < 8; j++) {
            uint4 kf = kpkb[(w + 8 * j) * 32 + lane];
            // two independent chains per group: c1 (2-deep), c2 (1-deep)
            float cA1[4] = {0.f, 0.f, 0.f, 0.f};
            float cA2[4] = {0.f, 0.f, 0.f, 0.f};
            float cB1[4] = {0.f, 0.f, 0.f, 0.f};
            float cB2[4] = {0.f, 0.f, 0.f, 0.f};
            mma8(cA1, kf.x, kf.y, qAh);   // Khi.qhi
            mma8(cB1, kf.x, kf.y, qBh);
            mma8(cA2, kf.x, kf.y, qAl);   // Khi.qlo (independent)
            mma8(cB2, kf.x, kf.y, qBl);
            mma8(cA1, kf.z, kf.w, qAh);   // Klo.qhi (chains on cA1)
            mma8(cB1, kf.z, kf.w, qBh);
            float pA0 = __expf(cA1[0] + cA2[0]);
            float pA1 = __expf(cA1[1] + cA2[1]);
            float pA2 = __expf(cA1[2] + cA2[2]);
            float pA3 = __expf(cA1[3] + cA2[3]);
            float pB0 = __expf(cB1[0] + cB2[0]);
            float pB1 = __expf(cB1[1] + cB2[1]);
            float pB2 = __expf(cB1[2] + cB2[2]);
            float pB3 = __expf(cB1[3] + cB2[3]);
            d0A += pA0 + pA2;  d1A += pA1 + pA3;
            d0B += pB0 + pB2;  d1B += pB1 + pB3;
            paA0[j] = h2u(__floats2half2_rn(pA0, pA1));
            paA1[j] = h2u(__floats2half2_rn(pA2, pA3));
            paB0[j] = h2u(__floats2half2_rn(pB0, pB1));
            paB1[j] = h2u(__floats2half2_rn(pB2, pB3));
        }

#pragma unroll
        for (int m = 4; m <= 16; m <<= 1) {
            d0A += __shfl_xor_sync(0xFFFFFFFFu, d0A, m);
            d1A += __shfl_xor_sync(0xFFFFFFFFu, d1A, m);
            d0B += __shfl_xor_sync(0xFFFFFFFFu, d0B, m);
            d1B += __shfl_xor_sync(0xFFFFFFFFu, d1B, m);
        }
        if (lane < 4) {
            rp[w * 16 + 2 * t]         = d0A;
            rp[w * 16 + 2 * t + 1]     = d1A;
            rp[w * 16 + 8 + 2 * t]     = d0B;
            rp[w * 16 + 8 + 2 * t + 1] = d1B;
        }
        __syncthreads();

        float D0A = 0.f, D1A = 0.f, D0B = 0.f, D1B = 0.f;
#pragma unroll
        for (int ww = 0; ww < 8; ww++) {
            D0A += rp[ww * 16 + 2 * t];
            D1A += rp[ww * 16 + 2 * t + 1];
            D0B += rp[ww * 16 + 8 + 2 * t];
            D1B += rp[ww * 16 + 8 + 2 * t + 1];
        }

        float vA0 = vb[(size_t)(eA + 2 * t) * HDIM + g] / D0A;
        float vA1 = vb[(size_t)(eA + 2 * t + 1) * HDIM + g] / D1A;
        float vB0 = vb[(size_t)(eB + 2 * t) * HDIM + g] / D0B;
        float vB1 = vb[(size_t)(eB + 2 * t + 1) * HDIM + g] / D1B;
        uint32_t bvA = h2u(__floats2half2_rn(vA0, vA1));
        uint32_t bvB = h2u(__floats2half2_rn(vB0, vB1));

#pragma unroll
        for (int j = 0; j < 8; j++) {
            mma8(out[j], paA0[j], paA1[j], bvA);
            mma8(out[j], paB0[j], paB1[j], bvB);
        }
        // no trailing sync: red parity double-buffered.
    }

    float* op = g_opart + ((size_t)(b * ECHUNKS + ec)) * (CDIM * HDIM);
#pragma unroll
    for (int j = 0; j < 8; j++) {
        const int c = (w + 8 * j) * 16 + g;
        *(float2*)(op + (size_t)c * HDIM + 2 * t)       = make_float2(out[j][0], out[j][1]);
        *(float2*)(op + (size_t)(c + 8) * HDIM + 2 * t) = make_float2(out[j][2], out[j][3]);
    }
}

// ---------------------------------------------------------------------------
// Kernel 4: final reduce over e-chunks -> d_out
// ---------------------------------------------------------------------------
__global__ void final_reduce_kernel(float* __restrict__ out)
{
    const int f = blockIdx.x * blockDim.x + threadIdx.x;
    const int b = f >> 11;
    const int r = f & 2047;

    const float4* gp = (const float4*)g_opart;
    float4 s = make_float4(0.f, 0.f, 0.f, 0.f);
#pragma unroll
    for (int ec = 0; ec < ECHUNKS; ec++) {
        float4 v = gp[(size_t)(b * ECHUNKS + ec) * 2048 + r];
        s.x += v.x; s.y += v.y; s.z += v.z; s.w += v.w;
    }
    ((float4*)out)[f] = s;
}

// ---------------------------------------------------------------------------
// Launch
// ---------------------------------------------------------------------------
extern "C" void kernel_launch(void* const* d_in, const int* in_sizes, int n_in,
                              void* d_out, int out_size)
{
    const float* x  = (const float*)d_in[0];
    const float* Wq = (const float*)d_in[1];
    const float* bq = (const float*)d_in[2];
    const float* Wk = (const float*)d_in[3];
    const float* bk = (const float*)d_in[4];
    const float* Wv = (const float*)d_in[5];
    const float* bv = (const float*)d_in[6];
    float* out = (float*)d_out;

    static int smem_set = 0;
    if (!smem_set) {
        cudaFuncSetAttribute(qkv_hmma_kernel,
                             cudaFuncAttributeMaxDynamicSharedMemorySize,
                             SMEM_BYTES);
        smem_set = 1;
    }

    pack_x_kernel<<<256, 256>>>(x);

    dim3 g1(NTOT / BN, KSPLIT);                 // (192, 8)
    qkv_hmma_kernel<<<g1, GEMM_THREADS, SMEM_BYTES>>>(Wq, Wk, Wv);

    reduce_bias_kernel<<<768, 256>>>(bq, bk, bv);

    dim3 g3(BATCH, ECHUNKS);                    // (32, 8)
    attention_kernel<<<g3, ATT_THREADS>>>();

    final_reduce_kernel<<<(BATCH * CDIM * HDIM / 4) / 256, 256>>>(out);
}

// round 16
// speedup vs baseline: 1.0017x; 1.0017x over previous
#include <cuda_runtime.h>
#include <cuda_bf16.h>
#include <cuda_fp16.h>
#include <math.h>
#include <stdint.h>

// ---------------------------------------------------------------------------
// Problem constants
// ---------------------------------------------------------------------------
#define BATCH   32
#define CDIM    1024
#define HDIM    8
#define INF     8192
#define OUTF    8192
#define NTOT    (3 * OUTF)      // 24576 (q | k | v columns)
#define DK      8

// HMMA GEMM tiling: KSPLIT=16 -> 3072 blocks = 6.92 waves at occ 3 (was 3.46)
#define BN      128
#define KSPLIT  16
#define KCHUNK  (INF / KSPLIT)  // 512
#define KBLK    32
#define NSTAGES (KCHUNK / KBLK) // 16
#define PIPEW   3
#define GEMM_THREADS 256
#define WSTR    40
#define STAGEF  (16 * WSTR)
#define SMEM_BYTES (8 * PIPEW * STAGEF * 4)   // 61440

// Attention
#define ECHUNKS 8
#define EROWS   (CDIM / ECHUNKS)  // 128
#define ATT_THREADS 256

// ---------------------------------------------------------------------------
// Device scratch
// ---------------------------------------------------------------------------
__device__ float g_part[KSPLIT * BATCH * NTOT];          // 50 MB gemm partials
__device__ float g_qkv[BATCH * NTOT];                    // 3 MB
__device__ float g_opart[BATCH * ECHUNKS * CDIM * HDIM]; // 8.4 MB
// x packed in mma-B-fragment order, hi/lo interleaved per fragment
__device__ uint4 g_xpk[512 * 4 * 32];                    // 1 MB
// K packed in mma-A-fragment order (fp16 hi/lo, scale 1/sqrt(8) folded)
__device__ uint4 g_kpk[BATCH * 64 * 32];                 // 1 MB

// ---------------------------------------------------------------------------
// Helpers
// ---------------------------------------------------------------------------
__device__ __forceinline__ void mma_bf16(float* c,
                                         uint32_t a0, uint32_t a1, uint32_t a2, uint32_t a3,
                                         uint32_t b0, uint32_t b1) {
    asm volatile(
        "mma.sync.aligned.m16n8k16.row.col.f32.bf16.bf16.f32 "
        "{%0,%1,%2,%3}, {%4,%5,%6,%7}, {%8,%9}, {%0,%1,%2,%3};"
        : "+f"(c[0]), "+f"(c[1]), "+f"(c[2]), "+f"(c[3])
        : "r"(a0), "r"(a1), "r"(a2), "r"(a3), "r"(b0), "r"(b1));
}

// m16n8k8 fp16 mma, fp32 accumulate
__device__ __forceinline__ void mma8(float* c, uint32_t a0, uint32_t a1, uint32_t b0) {
    asm volatile(
        "mma.sync.aligned.m16n8k8.row.col.f32.f16.f16.f32 "
        "{%0,%1,%2,%3}, {%4,%5}, {%6}, {%0,%1,%2,%3};"
        : "+f"(c[0]), "+f"(c[1]), "+f"(c[2]), "+f"(c[3])
        : "r"(a0), "r"(a1), "r"(b0));
}

// split fp32 pair -> (hi bf16x2 via truncation, lo bf16x2 rn)   [GEMM path]
__device__ __forceinline__ void split2(float2 v, uint32_t& hi, uint32_t& lo) {
    uint32_t u0 = __float_as_uint(v.x);
    uint32_t u1 = __float_as_uint(v.y);
    hi = __byte_perm(u0, u1, 0x7632);
    float h0 = __uint_as_float(u0 & 0xFFFF0000u);
    float h1 = __uint_as_float(u1 & 0xFFFF0000u);
    float l0 = v.x - h0;
    float l1 = v.y - h1;
    asm("cvt.rn.bf16x2.f32 %0, %1, %2;" : "=r"(lo) : "f"(l1), "f"(l0));
}

__device__ __forceinline__ uint32_t h2u(__half2 h) {
    return *reinterpret_cast<uint32_t*>(&h);
}

// split fp32 pair -> fp16x2 hi (rn) + fp16x2 lo (rn of residual)
__device__ __forceinline__ void split2h(float a, float b, uint32_t& hi, uint32_t& lo) {
    __half2 h = __floats2half2_rn(a, b);
    float2 f = __half22float2(h);
    __half2 l = __floats2half2_rn(a - f.x, b - f.y);
    hi = h2u(h); lo = h2u(l);
}

__device__ __forceinline__ uint32_t smem_u32(const void* p) {
    uint32_t a;
    asm("{ .reg .u64 t; cvta.to.shared.u64 t, %1; cvt.u32.u64 %0, t; }"
        : "=r"(a) : "l"(p));
    return a;
}

__device__ __forceinline__ void cp16(uint32_t daddr, const void* src) {
    asm volatile("cp.async.cg.shared.global [%0], [%1], 16;"
                 :: "r"(daddr), "l"(src) : "memory");
}

// ---------------------------------------------------------------------------
// Kernel 0: pack x fp32 -> bf16 hi/lo B-fragments, hi/lo interleaved
// ---------------------------------------------------------------------------
__global__ void pack_x_kernel(const float* __restrict__ x)
{
    int t    = blockIdx.x * blockDim.x + threadIdx.x;
    int lane = t & 31;
    int nb   = (t >> 5) & 3;
    int kb   = t >> 7;

    int n    = nb * 8 + (lane >> 2);
    int kcol = kb * 16 + 2 * (lane & 3);

    const float* xr = x + (size_t)n * INF + kcol;
    float2 v0 = *(const float2*)xr;
    float2 v1 = *(const float2*)(xr + 8);

    uint32_t h0, l0, h1, l1;
    split2(v0, h0, l0);
    split2(v1, h1, l1);

    g_xpk[(size_t)(kb * 4 + nb) * 32 + lane] = make_uint4(h0, h1, l0, l1);
}

// ---------------------------------------------------------------------------
// Kernel 1: QKV GEMM (per-warp cp.async depth-3, occ 3; x-frags via LDG.128)
// ---------------------------------------------------------------------------
__global__ void __launch_bounds__(GEMM_THREADS, 3)
qkv_hmma_kernel(const float* __restrict__ Wq,
                const float* __restrict__ Wk,
                const float* __restrict__ Wv)
{
    extern __shared__ __align__(16) float sW[];

    const int tid  = threadIdx.x;
    const int wid  = tid >> 5;
    const int lane = tid & 31;
    const int g    = lane >> 2;
    const int q    = lane & 3;

    const int nt = blockIdx.x;
    const int kc = blockIdx.y;
    const int wsel = nt >> 6;
    const float* __restrict__ W = (wsel == 0) ? Wq : ((wsel == 1) ? Wk : Wv);
    const int n0     = (nt & 63) * BN;
    const int nglob0 = nt * BN;
    const int kbase  = kc * KCHUNK;
    const int kb0    = kc * (KCHUNK / 16);

    float* wtile = sW + wid * (PIPEW * STAGEF);

    const int lr = lane >> 1;
    const int lh = (lane & 1) * 16;
    const float* wsrc = W + (size_t)(n0 + wid * 16 + lr) * INF + kbase + lh;
    const uint32_t swb = smem_u32(wtile) + (uint32_t)(lr * WSTR + lh) * 4;

    const uint4* __restrict__ xpk = g_xpk;

    float c[4][4];
#pragma unroll
    for (int i = 0; i < 4; i++)
#pragma unroll
        for (int j = 0; j < 4; j++) c[i][j] = 0.0f;

#define ISSUE(T)                                                              \
    do {                                                                      \
        int _t = (T);                                                         \
        if (_t < NSTAGES) {                                                   \
            uint32_t _d = swb + (_t % PIPEW) * (STAGEF * 4);                  \
            const float* _s = wsrc + _t * KBLK;                               \
            cp16(_d,      _s);                                                \
            cp16(_d + 16, _s + 4);                                            \
            cp16(_d + 32, _s + 8);                                            \
            cp16(_d + 48, _s + 12);                                           \
        }                                                                     \
        asm volatile("cp.async.commit_group;" ::: "memory");                  \
    } while (0)

    ISSUE(0);
    ISSUE(1);

#pragma unroll 1
    for (int t = 0; t < NSTAGES; t++) {
        asm volatile("cp.async.wait_group 1;" ::: "memory");
        __syncwarp();

        ISSUE(t + 2);

        const float* Ws = wtile + (t % PIPEW) * STAGEF;

#pragma unroll
        for (int ks = 0; ks < 2; ks++) {
            const int kb = kb0 + t * 2 + ks;
            const int fA = g * WSTR + ks * 16 + 2 * q;
            float2 p0 = *(const float2*)(Ws + fA);
            float2 p1 = *(const float2*)(Ws + fA + 8 * WSTR);
            float2 p2 = *(const float2*)(Ws + fA + 8);
            float2 p3 = *(const float2*)(Ws + fA + 8 * WSTR + 8);
            uint32_t ah0, al0, ah1, al1, ah2, al2, ah3, al3;
            split2(p0, ah0, al0);
            split2(p1, ah1, al1);
            split2(p2, ah2, al2);
            split2(p3, ah3, al3);
#pragma unroll
            for (int n2 = 0; n2 < 4; n2++) {
                uint4 bx = xpk[(size_t)(kb * 4 + n2) * 32 + lane];
                mma_bf16(c[n2], ah0, ah1, ah2, ah3, bx.x, bx.y);
                mma_bf16(c[n2], ah0, ah1, ah2, ah3, bx.z, bx.w);
                mma_bf16(c[n2], al0, al1, al2, al3, bx.x, bx.y);
            }
        }
    }
#undef ISSUE

    float* P = g_part + (size_t)kc * (BATCH * NTOT);
    const int n_lo = nglob0 + wid * 16 + g;
    const int n_hi = n_lo + 8;
#pragma unroll
    for (int n2 = 0; n2 < 4; n2++) {
        const int b0 = n2 * 8 + 2 * q;
        P[(size_t)b0 * NTOT + n_lo]       = c[n2][0];
        P[(size_t)(b0 + 1) * NTOT + n_lo] = c[n2][1];
        P[(size_t)b0 * NTOT + n_hi]       = c[n2][2];
        P[(size_t)(b0 + 1) * NTOT + n_hi] = c[n2][3];
    }
}

// ---------------------------------------------------------------------------
// Kernel 2: reduce K-chunk partials + bias -> g_qkv, AND scatter packed
//   fp16 hi/lo K-fragments into g_kpk. 1 float4/thread, grid 768.
// ---------------------------------------------------------------------------
__global__ void reduce_bias_kernel(const float* __restrict__ bq,
                                   const float* __restrict__ bk,
                                   const float* __restrict__ bv)
{
    const int idx4 = blockIdx.x * blockDim.x + threadIdx.x;  // 0..196607
    const int flat = idx4 * 4;
    const int bb   = flat / NTOT;
    const int n    = flat % NTOT;

    uint32_t* kpk32 = (uint32_t*)g_kpk;
    const float4* P = (const float4*)g_part;

    float4 s = P[idx4];
#pragma unroll
    for (int kc = 1; kc < KSPLIT; kc++) {
        float4 v = P[idx4 + (size_t)kc * (BATCH * NTOT / 4)];
        s.x += v.x; s.y += v.y; s.z += v.z; s.w += v.w;
    }

    const int wsel = n / OUTF;
    const int nr   = n % OUTF;
    const float* bias = (wsel == 0) ? bq : ((wsel == 1) ? bk : bv);
    float4 bbv = *(const float4*)&bias[nr];
    s.x += bbv.x; s.y += bbv.y; s.z += bbv.z; s.w += bbv.w;

    ((float4*)g_qkv)[idx4] = s;

    if (wsel == 1) {
        const int r  = nr >> 3;
        const int j  = (nr & 7) >> 2;
        const int tile = r >> 4;
        const int rr   = r & 15;
        const int comp = rr >> 3;
        const int g    = rr & 7;
        const float sc = 0.35355339059327373f;   // 1/sqrt(8)

        uint32_t h0, l0, h1, l1;
        split2h(s.x * sc, s.y * sc, h0, l0);
        split2h(s.z * sc, s.w * sc, h1, l1);
        const int t0 = 2 * j;
        uint32_t base0 = (((uint32_t)(bb * 64 + tile) * 32) + (g * 4 + t0)) * 4;
        uint32_t base1 = base0 + 4;
        kpk32[base0 + comp]     = h0;
        kpk32[base0 + 2 + comp] = l0;
        kpk32[base1 + comp]     = h1;
        kpk32[base1 + 2 + comp] = l1;
    }
}

// ---------------------------------------------------------------------------
// Kernel 3: HMMA attention (R14 body — fastest measured variant).
//   Double-pass (16 e's per round), parity-buffered reduce, one sync/round.
// ---------------------------------------------------------------------------
__global__ void __launch_bounds__(ATT_THREADS, 2)
attention_kernel()
{
    __shared__ float red[2][128];   // [parity][warp*16 + idx]

    const int tid  = threadIdx.x;
    const int w    = tid >> 5;
    const int lane = tid & 31;
    const int g    = lane >> 2;
    const int t    = lane & 3;
    const int b    = blockIdx.x;
    const int ec   = blockIdx.y;

    const float* __restrict__ qb = g_qkv + (size_t)b * NTOT;
    const float* __restrict__ vb = qb + 2 * OUTF;
    const uint4* __restrict__ kpkb = g_kpk + (size_t)b * 2048;

    float out[8][4];
#pragma unroll
    for (int j = 0; j < 8; j++)
#pragma unroll
        for (int i = 0; i < 4; i++) out[j][i] = 0.0f;

#pragma unroll 1
    for (int p = 0; p < EROWS / 16; p++) {     // 8 rounds of 16 e's
        const int eA = ec * EROWS + p * 16;
        const int eB = eA + 8;
        float* rp = red[p & 1];

        float2 qvA = *(const float2*)(qb + (size_t)(eA + g) * HDIM + 2 * t);
        float2 qvB = *(const float2*)(qb + (size_t)(eB + g) * HDIM + 2 * t);
        uint32_t qAh, qAl, qBh, qBl;
        split2h(qvA.x, qvA.y, qAh, qAl);
        split2h(qvB.x, qvB.y, qBh, qBl);

        uint32_t paA0[8], paA1[8], paB0[8], paB1[8];
        float d0A = 0.f, d1A = 0.f, d0B = 0.f, d1B = 0.f;

#pragma unroll
        for (int j = 0; j < 8; j++) {
            uint4 kf = kpkb[(w + 8 * j) * 32 + lane];
            float cA[4] = {0.f, 0.f, 0.f, 0.f};
            float cB[4] = {0.f, 0.f, 0.f, 0.f};
            mma8(cA, kf.x, kf.y, qAh);
            mma8(cB, kf.x, kf.y, qBh);
            mma8(cA, kf.x, kf.y, qAl);
            mma8(cB, kf.x, kf.y, qBl);
            mma8(cA, kf.z, kf.w, qAh);
            mma8(cB, kf.z, kf.w, qBh);
            float pA0 = __expf(cA[0]);
            float pA1 = __expf(cA[1]);
            float pA2 = __expf(cA[2]);
            float pA3 = __expf(cA[3]);
            float pB0 = __expf(cB[0]);
            float pB1 = __expf(cB[1]);
            float pB2 = __expf(cB[2]);
            float pB3 = __expf(cB[3]);
            d0A += pA0 + pA2;  d1A += pA1 + pA3;
            d0B += pB0 + pB2;  d1B += pB1 + pB3;
            paA0[j] = h2u(__floats2half2_rn(pA0, pA1));
            paA1[j] = h2u(__floats2half2_rn(pA2, pA3));
            paB0[j] = h2u(__floats2half2_rn(pB0, pB1));
            paB1[j] = h2u(__floats2half2_rn(pB2, pB3));
        }

#pragma unroll
        for (int m = 4; m <= 16; m <<= 1) {
            d0A += __shfl_xor_sync(0xFFFFFFFFu, d0A, m);
            d1A += __shfl_xor_sync(0xFFFFFFFFu, d1A, m);
            d0B += __shfl_xor_sync(0xFFFFFFFFu, d0B, m);
            d1B += __shfl_xor_sync(0xFFFFFFFFu, d1B, m);
        }
        if (lane < 4) {
            rp[w * 16 + 2 * t]         = d0A;
            rp[w * 16 + 2 * t + 1]     = d1A;
            rp[w * 16 + 8 + 2 * t]     = d0B;
            rp[w * 16 + 8 + 2 * t + 1] = d1B;
        }
        __syncthreads();

        float D0A = 0.f, D1A = 0.f, D0B = 0.f, D1B = 0.f;
#pragma unroll
        for (int ww = 0; ww < 8; ww++) {
            D0A += rp[ww * 16 + 2 * t];
            D1A += rp[ww * 16 + 2 * t + 1];
            D0B += rp[ww * 16 + 8 + 2 * t];
            D1B += rp[ww * 16 + 8 + 2 * t + 1];
        }

        float vA0 = vb[(size_t)(eA + 2 * t) * HDIM + g] / D0A;
        float vA1 = vb[(size_t)(eA + 2 * t + 1) * HDIM + g] / D1A;
        float vB0 = vb[(size_t)(eB + 2 * t) * HDIM + g] / D0B;
        float vB1 = vb[(size_t)(eB + 2 * t + 1) * HDIM + g] / D1B;
        uint32_t bvA = h2u(__floats2half2_rn(vA0, vA1));
        uint32_t bvB = h2u(__floats2half2_rn(vB0, vB1));

#pragma unroll
        for (int j = 0; j < 8; j++) {
            mma8(out[j], paA0[j], paA1[j], bvA);
            mma8(out[j], paB0[j], paB1[j], bvB);
        }
        // no trailing sync: red parity double-buffered.
    }

    float* op = g_opart + ((size_t)(b * ECHUNKS + ec)) * (CDIM * HDIM);
#pragma unroll
    for (int j = 0; j < 8; j++) {
        const int c = (w + 8 * j) * 16 + g;
        *(float2*)(op + (size_t)c * HDIM + 2 * t)       = make_float2(out[j][0], out[j][1]);
        *(float2*)(op + (size_t)(c + 8) * HDIM + 2 * t) = make_float2(out[j][2], out[j][3]);
    }
}

// ---------------------------------------------------------------------------
// Kernel 4: final reduce over e-chunks -> d_out
// ---------------------------------------------------------------------------
__global__ void final_reduce_kernel(float* __restrict__ out)
{
    const int f = blockIdx.x * blockDim.x + threadIdx.x;
    const int b = f >> 11;
    const int r = f & 2047;

    const float4* gp = (const float4*)g_opart;
    float4 s = make_float4(0.f, 0.f, 0.f, 0.f);
#pragma unroll
    for (int ec = 0; ec < ECHUNKS; ec++) {
        float4 v = gp[(size_t)(b * ECHUNKS + ec) * 2048 + r];
        s.x += v.x; s.y += v.y; s.z += v.z; s.w += v.w;
    }
    ((float4*)out)[f] = s;
}

// ---------------------------------------------------------------------------
// Launch
// ---------------------------------------------------------------------------
extern "C" void kernel_launch(void* const* d_in, const int* in_sizes, int n_in,
                              void* d_out, int out_size)
{
    const float* x  = (const float*)d_in[0];
    const float* Wq = (const float*)d_in[1];
    const float* bq = (const float*)d_in[2];
    const float* Wk = (const float*)d_in[3];
    const float* bk = (const float*)d_in[4];
    const float* Wv = (const float*)d_in[5];
    const float* bv = (const float*)d_in[6];
    float* out = (float*)d_out;

    static int smem_set = 0;
    if (!smem_set) {
        cudaFuncSetAttribute(qkv_hmma_kernel,
                             cudaFuncAttributeMaxDynamicSharedMemorySize,
                             SMEM_BYTES);
        smem_set = 1;
    }

    pack_x_kernel<<<256, 256>>>(x);

    dim3 g1(NTOT / BN, KSPLIT);                 // (192, 16) = 3072 blocks
    qkv_hmma_kernel<<<g1, GEMM_THREADS, SMEM_BYTES>>>(Wq, Wk, Wv);

    reduce_bias_kernel<<<768, 256>>>(bq, bk, bv);

    dim3 g3(BATCH, ECHUNKS);                    // (32, 8)
    attention_kernel<<<g3, ATT_THREADS>>>();

    final_reduce_kernel<<<(BATCH * CDIM * HDIM / 4) / 256, 256>>>(out);
}

// round 17
// speedup vs baseline: 1.0210x; 1.0192x over previous
#include <cuda_runtime.h>
#include <cuda_bf16.h>
#include <cuda_fp16.h>
#include <math.h>
#include <stdint.h>

// ---------------------------------------------------------------------------
// Problem constants
// ---------------------------------------------------------------------------
#define BATCH   32
#define CDIM    1024
#define HDIM    8
#define INF     8192
#define OUTF    8192
#define NTOT    (3 * OUTF)      // 24576 (q | k | v columns)
#define DK      8

// HMMA GEMM tiling (KSPLIT 8: lower partial traffic; 16 measured neutral-worse)
#define BN      128
#define KSPLIT  8
#define KCHUNK  (INF / KSPLIT)  // 1024
#define KBLK    32
#define NSTAGES (KCHUNK / KBLK) // 32
#define PIPEW   3
#define GEMM_THREADS 256
#define WSTR    40
#define STAGEF  (16 * WSTR)
#define SMEM_BYTES (8 * PIPEW * STAGEF * 4)   // 61440

// Attention
#define ECHUNKS 8
#define EROWS   (CDIM / ECHUNKS)  // 128
#define ATT_THREADS 256

// ---------------------------------------------------------------------------
// Device scratch
// ---------------------------------------------------------------------------
__device__ float g_part[KSPLIT * BATCH * NTOT];          // 25 MB gemm partials
__device__ float g_qkv[BATCH * NTOT];                    // 3 MB
__device__ float g_opart[BATCH * ECHUNKS * CDIM * HDIM]; // 8.4 MB
// x packed in mma-B-fragment order, hi/lo interleaved per fragment
__device__ uint4 g_xpk[512 * 4 * 32];                    // 1 MB
// K packed in mma-A-fragment order (fp16 hi/lo, scale 1/sqrt(8) folded)
__device__ uint4 g_kpk[BATCH * 64 * 32];                 // 1 MB

// ---------------------------------------------------------------------------
// Helpers
// ---------------------------------------------------------------------------
__device__ __forceinline__ void mma_bf16(float* c,
                                         uint32_t a0, uint32_t a1, uint32_t a2, uint32_t a3,
                                         uint32_t b0, uint32_t b1) {
    asm volatile(
        "mma.sync.aligned.m16n8k16.row.col.f32.bf16.bf16.f32 "
        "{%0,%1,%2,%3}, {%4,%5,%6,%7}, {%8,%9}, {%0,%1,%2,%3};"
        : "+f"(c[0]), "+f"(c[1]), "+f"(c[2]), "+f"(c[3])
        : "r"(a0), "r"(a1), "r"(a2), "r"(a3), "r"(b0), "r"(b1));
}

// m16n8k8 fp16 mma, fp32 accumulate
__device__ __forceinline__ void mma8(float* c, uint32_t a0, uint32_t a1, uint32_t b0) {
    asm volatile(
        "mma.sync.aligned.m16n8k8.row.col.f32.f16.f16.f32 "
        "{%0,%1,%2,%3}, {%4,%5}, {%6}, {%0,%1,%2,%3};"
        : "+f"(c[0]), "+f"(c[1]), "+f"(c[2]), "+f"(c[3])
        : "r"(a0), "r"(a1), "r"(b0));
}

// split fp32 pair -> (hi bf16x2 via truncation, lo bf16x2 rn)   [GEMM path]
__device__ __forceinline__ void split2(float2 v, uint32_t& hi, uint32_t& lo) {
    uint32_t u0 = __float_as_uint(v.x);
    uint32_t u1 = __float_as_uint(v.y);
    hi = __byte_perm(u0, u1, 0x7632);
    float h0 = __uint_as_float(u0 & 0xFFFF0000u);
    float h1 = __uint_as_float(u1 & 0xFFFF0000u);
    float l0 = v.x - h0;
    float l1 = v.y - h1;
    asm("cvt.rn.bf16x2.f32 %0, %1, %2;" : "=r"(lo) : "f"(l1), "f"(l0));
}

__device__ __forceinline__ uint32_t h2u(__half2 h) {
    return *reinterpret_cast<uint32_t*>(&h);
}

// split fp32 pair -> fp16x2 hi (rn) + fp16x2 lo (rn of residual)
__device__ __forceinline__ void split2h(float a, float b, uint32_t& hi, uint32_t& lo) {
    __half2 h = __floats2half2_rn(a, b);
    float2 f = __half22float2(h);
    __half2 l = __floats2half2_rn(a - f.x, b - f.y);
    hi = h2u(h); lo = h2u(l);
}

__device__ __forceinline__ uint32_t smem_u32(const void* p) {
    uint32_t a;
    asm("{ .reg .u64 t; cvta.to.shared.u64 t, %1; cvt.u32.u64 %0, t; }"
        : "=r"(a) : "l"(p));
    return a;
}

__device__ __forceinline__ void cp16(uint32_t daddr, const void* src) {
    asm volatile("cp.async.cg.shared.global [%0], [%1], 16;"
                 :: "r"(daddr), "l"(src) : "memory");
}

// ---------------------------------------------------------------------------
// Kernel 0: pack x fp32 -> bf16 hi/lo B-fragments, hi/lo interleaved
// ---------------------------------------------------------------------------
__global__ void pack_x_kernel(const float* __restrict__ x)
{
    int t    = blockIdx.x * blockDim.x + threadIdx.x;
    int lane = t & 31;
    int nb   = (t >> 5) & 3;
    int kb   = t >> 7;

    int n    = nb * 8 + (lane >> 2);
    int kcol = kb * 16 + 2 * (lane & 3);

    const float* xr = x + (size_t)n * INF + kcol;
    float2 v0 = *(const float2*)xr;
    float2 v1 = *(const float2*)(xr + 8);

    uint32_t h0, l0, h1, l1;
    split2(v0, h0, l0);
    split2(v1, h1, l1);

    g_xpk[(size_t)(kb * 4 + nb) * 32 + lane] = make_uint4(h0, h1, l0, l1);
}

// ---------------------------------------------------------------------------
// Kernel 1: QKV GEMM (per-warp cp.async depth-3, occ 3; x-frags via LDG.128)
// ---------------------------------------------------------------------------
__global__ void __launch_bounds__(GEMM_THREADS, 3)
qkv_hmma_kernel(const float* __restrict__ Wq,
                const float* __restrict__ Wk,
                const float* __restrict__ Wv)
{
    extern __shared__ __align__(16) float sW[];

    const int tid  = threadIdx.x;
    const int wid  = tid >> 5;
    const int lane = tid & 31;
    const int g    = lane >> 2;
    const int q    = lane & 3;

    const int nt = blockIdx.x;
    const int kc = blockIdx.y;
    const int wsel = nt >> 6;
    const float* __restrict__ W = (wsel == 0) ? Wq : ((wsel == 1) ? Wk : Wv);
    const int n0     = (nt & 63) * BN;
    const int nglob0 = nt * BN;
    const int kbase  = kc * KCHUNK;
    const int kb0    = kc * (KCHUNK / 16);

    float* wtile = sW + wid * (PIPEW * STAGEF);

    const int lr = lane >> 1;
    const int lh = (lane & 1) * 16;
    const float* wsrc = W + (size_t)(n0 + wid * 16 + lr) * INF + kbase + lh;
    const uint32_t swb = smem_u32(wtile) + (uint32_t)(lr * WSTR + lh) * 4;

    const uint4* __restrict__ xpk = g_xpk;

    float c[4][4];
#pragma unroll
    for (int i = 0; i < 4; i++)
#pragma unroll
        for (int j = 0; j < 4; j++) c[i][j] = 0.0f;

#define ISSUE(T)                                                              \
    do {                                                                      \
        int _t = (T);                                                         \
        if (_t < NSTAGES) {                                                   \
            uint32_t _d = swb + (_t % PIPEW) * (STAGEF * 4);                  \
            const float* _s = wsrc + _t * KBLK;                               \
            cp16(_d,      _s);                                                \
            cp16(_d + 16, _s + 4);                                            \
            cp16(_d + 32, _s + 8);                                            \
            cp16(_d + 48, _s + 12);                                           \
        }                                                                     \
        asm volatile("cp.async.commit_group;" ::: "memory");                  \
    } while (0)

    ISSUE(0);
    ISSUE(1);

#pragma unroll 1
    for (int t = 0; t < NSTAGES; t++) {
        asm volatile("cp.async.wait_group 1;" ::: "memory");
        __syncwarp();

        ISSUE(t + 2);

        const float* Ws = wtile + (t % PIPEW) * STAGEF;

#pragma unroll
        for (int ks = 0; ks < 2; ks++) {
            const int kb = kb0 + t * 2 + ks;
            const int fA = g * WSTR + ks * 16 + 2 * q;
            float2 p0 = *(const float2*)(Ws + fA);
            float2 p1 = *(const float2*)(Ws + fA + 8 * WSTR);
            float2 p2 = *(const float2*)(Ws + fA + 8);
            float2 p3 = *(const float2*)(Ws + fA + 8 * WSTR + 8);
            uint32_t ah0, al0, ah1, al1, ah2, al2, ah3, al3;
            split2(p0, ah0, al0);
            split2(p1, ah1, al1);
            split2(p2, ah2, al2);
            split2(p3, ah3, al3);
#pragma unroll
            for (int n2 = 0; n2 < 4; n2++) {
                uint4 bx = xpk[(size_t)(kb * 4 + n2) * 32 + lane];
                mma_bf16(c[n2], ah0, ah1, ah2, ah3, bx.x, bx.y);
                mma_bf16(c[n2], ah0, ah1, ah2, ah3, bx.z, bx.w);
                mma_bf16(c[n2], al0, al1, al2, al3, bx.x, bx.y);
            }
        }
    }
#undef ISSUE

    float* P = g_part + (size_t)kc * (BATCH * NTOT);
    const int n_lo = nglob0 + wid * 16 + g;
    const int n_hi = n_lo + 8;
#pragma unroll
    for (int n2 = 0; n2 < 4; n2++) {
        const int b0 = n2 * 8 + 2 * q;
        P[(size_t)b0 * NTOT + n_lo]       = c[n2][0];
        P[(size_t)(b0 + 1) * NTOT + n_lo] = c[n2][1];
        P[(size_t)b0 * NTOT + n_hi]       = c[n2][2];
        P[(size_t)(b0 + 1) * NTOT + n_hi] = c[n2][3];
    }
}

// ---------------------------------------------------------------------------
// Kernel 2: reduce K-chunk partials + bias -> g_qkv, AND scatter packed
//   fp16 hi/lo K-fragments into g_kpk. 1 float4/thread, grid 768.
// ---------------------------------------------------------------------------
__global__ void reduce_bias_kernel(const float* __restrict__ bq,
                                   const float* __restrict__ bk,
                                   const float* __restrict__ bv)
{
    const int idx4 = blockIdx.x * blockDim.x + threadIdx.x;  // 0..196607
    const int flat = idx4 * 4;
    const int bb   = flat / NTOT;
    const int n    = flat % NTOT;

    uint32_t* kpk32 = (uint32_t*)g_kpk;
    const float4* P = (const float4*)g_part;

    float4 s = P[idx4];
#pragma unroll
    for (int kc = 1; kc < KSPLIT; kc++) {
        float4 v = P[idx4 + (size_t)kc * (BATCH * NTOT / 4)];
        s.x += v.x; s.y += v.y; s.z += v.z; s.w += v.w;
    }

    const int wsel = n / OUTF;
    const int nr   = n % OUTF;
    const float* bias = (wsel == 0) ? bq : ((wsel == 1) ? bk : bv);
    float4 bbv = *(const float4*)&bias[nr];
    s.x += bbv.x; s.y += bbv.y; s.z += bbv.z; s.w += bbv.w;

    ((float4*)g_qkv)[idx4] = s;

    if (wsel == 1) {
        const int r  = nr >> 3;
        const int j  = (nr & 7) >> 2;
        const int tile = r >> 4;
        const int rr   = r & 15;
        const int comp = rr >> 3;
        const int g    = rr & 7;
        const float sc = 0.35355339059327373f;   // 1/sqrt(8)

        uint32_t h0, l0, h1, l1;
        split2h(s.x * sc, s.y * sc, h0, l0);
        split2h(s.z * sc, s.w * sc, h1, l1);
        const int t0 = 2 * j;
        uint32_t base0 = (((uint32_t)(bb * 64 + tile) * 32) + (g * 4 + t0)) * 4;
        uint32_t base1 = base0 + 4;
        kpk32[base0 + comp]     = h0;
        kpk32[base0 + 2 + comp] = l0;
        kpk32[base1 + comp]     = h1;
        kpk32[base1 + 2 + comp] = l1;
    }
}

// ---------------------------------------------------------------------------
// Kernel 3: HMMA attention (R14 body + v-prefetch: the raw v loads for each
//   round are hoisted to the round top, off the post-sync critical path).
// ---------------------------------------------------------------------------
__global__ void __launch_bounds__(ATT_THREADS, 2)
attention_kernel()
{
    __shared__ float red[2][128];   // [parity][warp*16 + idx]

    const int tid  = threadIdx.x;
    const int w    = tid >> 5;
    const int lane = tid & 31;
    const int g    = lane >> 2;
    const int t    = tid & 3;
    const int b    = blockIdx.x;
    const int ec   = blockIdx.y;

    const float* __restrict__ qb = g_qkv + (size_t)b * NTOT;
    const float* __restrict__ vb = qb + 2 * OUTF;
    const uint4* __restrict__ kpkb = g_kpk + (size_t)b * 2048;

    float out[8][4];
#pragma unroll
    for (int j = 0; j < 8; j++)
#pragma unroll
        for (int i = 0; i < 4; i++) out[j][i] = 0.0f;

#pragma unroll 1
    for (int p = 0; p < EROWS / 16; p++) {     // 8 rounds of 16 e's
        const int eA = ec * EROWS + p * 16;
        const int eB = eA + 8;
        float* rp = red[p & 1];

        // --- prefetch q AND raw v rows for this round (off critical path) ---
        float2 qvA = *(const float2*)(qb + (size_t)(eA + g) * HDIM + 2 * t);
        float2 qvB = *(const float2*)(qb + (size_t)(eB + g) * HDIM + 2 * t);
        float vA0r = vb[(size_t)(eA + 2 * t) * HDIM + g];
        float vA1r = vb[(size_t)(eA + 2 * t + 1) * HDIM + g];
        float vB0r = vb[(size_t)(eB + 2 * t) * HDIM + g];
        float vB1r = vb[(size_t)(eB + 2 * t + 1) * HDIM + g];

        uint32_t qAh, qAl, qBh, qBl;
        split2h(qvA.x, qvA.y, qAh, qAl);
        split2h(qvB.x, qvB.y, qBh, qBl);

        uint32_t paA0[8], paA1[8], paB0[8], paB1[8];
        float d0A = 0.f, d1A = 0.f, d0B = 0.f, d1B = 0.f;

#pragma unroll
        for (int j = 0; j < 8; j++) {
            uint4 kf = kpkb[(w + 8 * j) * 32 + lane];
            float cA[4] = {0.f, 0.f, 0.f, 0.f};
            float cB[4] = {0.f, 0.f, 0.f, 0.f};
            mma8(cA, kf.x, kf.y, qAh);
            mma8(cB, kf.x, kf.y, qBh);
            mma8(cA, kf.x, kf.y, qAl);
            mma8(cB, kf.x, kf.y, qBl);
            mma8(cA, kf.z, kf.w, qAh);
            mma8(cB, kf.z, kf.w, qBh);
            float pA0 = __expf(cA[0]);
            float pA1 = __expf(cA[1]);
            float pA2 = __expf(cA[2]);
            float pA3 = __expf(cA[3]);
            float pB0 = __expf(cB[0]);
            float pB1 = __expf(cB[1]);
            float pB2 = __expf(cB[2]);
            float pB3 = __expf(cB[3]);
            d0A += pA0 + pA2;  d1A += pA1 + pA3;
            d0B += pB0 + pB2;  d1B += pB1 + pB3;
            paA0[j] = h2u(__floats2half2_rn(pA0, pA1));
            paA1[j] = h2u(__floats2half2_rn(pA2, pA3));
            paB0[j] = h2u(__floats2half2_rn(pB0, pB1));
            paB1[j] = h2u(__floats2half2_rn(pB2, pB3));
        }

#pragma unroll
        for (int m = 4; m <= 16; m <<= 1) {
            d0A += __shfl_xor_sync(0xFFFFFFFFu, d0A, m);
            d1A += __shfl_xor_sync(0xFFFFFFFFu, d1A, m);
            d0B += __shfl_xor_sync(0xFFFFFFFFu, d0B, m);
            d1B += __shfl_xor_sync(0xFFFFFFFFu, d1B, m);
        }
        if (lane < 4) {
            rp[w * 16 + 2 * t]         = d0A;
            rp[w * 16 + 2 * t + 1]     = d1A;
            rp[w * 16 + 8 + 2 * t]     = d0B;
            rp[w * 16 + 8 + 2 * t + 1] = d1B;
        }
        __syncthreads();

        float D0A = 0.f, D1A = 0.f, D0B = 0.f, D1B = 0.f;
#pragma unroll
        for (int ww = 0; ww < 8; ww++) {
            D0A += rp[ww * 16 + 2 * t];
            D1A += rp[ww * 16 + 2 * t + 1];
            D0B += rp[ww * 16 + 8 + 2 * t];
            D1B += rp[ww * 16 + 8 + 2 * t + 1];
        }

        uint32_t bvA = h2u(__floats2half2_rn(vA0r / D0A, vA1r / D1A));
        uint32_t bvB = h2u(__floats2half2_rn(vB0r / D0B, vB1r / D1B));

#pragma unroll
        for (int j = 0; j < 8; j++) {
            mma8(out[j], paA0[j], paA1[j], bvA);
            mma8(out[j], paB0[j], paB1[j], bvB);
        }
        // no trailing sync: red parity double-buffered.
    }

    float* op = g_opart + ((size_t)(b * ECHUNKS + ec)) * (CDIM * HDIM);
#pragma unroll
    for (int j = 0; j < 8; j++) {
        const int c = (w + 8 * j) * 16 + g;
        *(float2*)(op + (size_t)c * HDIM + 2 * t)       = make_float2(out[j][0], out[j][1]);
        *(float2*)(op + (size_t)(c + 8) * HDIM + 2 * t) = make_float2(out[j][2], out[j][3]);
    }
}

// ---------------------------------------------------------------------------
// Kernel 4: final reduce over e-chunks -> d_out
// ---------------------------------------------------------------------------
__global__ void final_reduce_kernel(float* __restrict__ out)
{
    const int f = blockIdx.x * blockDim.x + threadIdx.x;
    const int b = f >> 11;
    const int r = f & 2047;

    const float4* gp = (const float4*)g_opart;
    float4 s = make_float4(0.f, 0.f, 0.f, 0.f);
#pragma unroll
    for (int ec = 0; ec < ECHUNKS; ec++) {
        float4 v = gp[(size_t)(b * ECHUNKS + ec) * 2048 + r];
        s.x += v.x; s.y += v.y; s.z += v.z; s.w += v.w;
    }
    ((float4*)out)[f] = s;
}

// ---------------------------------------------------------------------------
// Launch
// ---------------------------------------------------------------------------
extern "C" void kernel_launch(void* const* d_in, const int* in_sizes, int n_in,
                              void* d_out, int out_size)
{
    const float* x  = (const float*)d_in[0];
    const float* Wq = (const float*)d_in[1];
    const float* bq = (const float*)d_in[2];
    const float* Wk = (const float*)d_in[3];
    const float* bk = (const float*)d_in[4];
    const float* Wv = (const float*)d_in[5];
    const float* bv = (const float*)d_in[6];
    float* out = (float*)d_out;

    static int smem_set = 0;
    if (!smem_set) {
        cudaFuncSetAttribute(qkv_hmma_kernel,
                             cudaFuncAttributeMaxDynamicSharedMemorySize,
                             SMEM_BYTES);
        smem_set = 1;
    }

    pack_x_kernel<<<256, 256>>>(x);

    dim3 g1(NTOT / BN, KSPLIT);                 // (192, 8)
    qkv_hmma_kernel<<<g1, GEMM_THREADS, SMEM_BYTES>>>(Wq, Wk, Wv);

    reduce_bias_kernel<<<768, 256>>>(bq, bk, bv);

    dim3 g3(BATCH, ECHUNKS);                    // (32, 8)
    attention_kernel<<<g3, ATT_THREADS>>>();

    final_reduce_kernel<<<(BATCH * CDIM * HDIM / 4) / 256, 256>>>(out);
}